// round 5
// baseline (speedup 1.0000x reference)
#include <cuda_runtime.h>
#include <cuda_bf16.h>
#include <cstdint>

// ---------------- problem constants ----------------
#define MAXN   200000
#define MAXE   500000
#define F_IN_  165
#define HID_   256
#define KTOT   330
#define APAD   192            // fp32 agg row stride
#define KPAD   352            // padded K (11 chunks of 32)
#define BK     32
#define NITER  (KPAD / BK)    // 11

// ---------------- device scratch ----------------
__device__ __align__(16) float g_agg[(size_t)MAXN * APAD];   // mean-agg (invd folded)
__device__ float g_deg[MAXN];                                // stores 1/max(deg,1)
__device__ __align__(16) float g_t  [MAXN * 2];
__device__ __align__(16) float g_rr [MAXN * 2];
__device__ __align__(16) __nv_bfloat16 g_Bhi[HID_ * KPAD];
__device__ __align__(16) __nv_bfloat16 g_Blo[HID_ * KPAD];
__device__ int g_ei[2 * MAXE];
__device__ int g_is64;
// CSR build
__device__ int g_cnt[MAXN];
__device__ int g_fc[MAXN];
__device__ int g_rowstart[MAXN + 1];
__device__ int g_blocksum[256];
__device__ int g_csr[MAXE];

// ---------------- PTX helpers (base-ISA; tcgen05 is sm_103a-gated, unusable here) ----------------
__device__ __forceinline__ uint32_t smem_u32(const void* p) {
    uint32_t a;
    asm("{ .reg .u64 t; cvta.to.shared.u64 t, %1; cvt.u32.u64 %0, t; }" : "=r"(a) : "l"(p));
    return a;
}
__device__ __forceinline__ void ldsm4(uint32_t& r0, uint32_t& r1, uint32_t& r2, uint32_t& r3,
                                      uint32_t addr) {
    asm volatile("ldmatrix.sync.aligned.m8n8.x4.shared.b16 {%0,%1,%2,%3}, [%4];"
                 : "=r"(r0), "=r"(r1), "=r"(r2), "=r"(r3) : "r"(addr));
}
// NOTE: non-volatile — pure register in/out; lets ptxas schedule around RAW latency.
#define MMA16816(c, a0, a1, a2, a3, b0, b1)                                            \
    asm("mma.sync.aligned.m16n8k16.row.col.f32.bf16.bf16.f32 "                         \
        "{%0,%1,%2,%3}, {%4,%5,%6,%7}, {%8,%9}, {%0,%1,%2,%3};"                        \
        : "+f"((c)[0]), "+f"((c)[1]), "+f"((c)[2]), "+f"((c)[3])                       \
        : "r"(a0), "r"(a1), "r"(a2), "r"(a3), "r"(b0), "r"(b1))
#define CP16(dst, src, pred)                                                           \
    asm volatile("cp.async.cg.shared.global [%0], [%1], 16, %2;"                       \
                 :: "r"(dst), "l"(src), "r"((pred) ? 16 : 0) : "memory")
#define CP_COMMIT() asm volatile("cp.async.commit_group;" ::: "memory")
#define CP_WAIT(n)  asm volatile("cp.async.wait_group %0;" :: "n"(n) : "memory")

// ---------------- edge index canon ----------------
__global__ void detect_kernel(const void* ei, int twoE) {
    const int* p = (const int*)ei;
    int nz = 0;
    for (int i = threadIdx.x; i < 256; i += 32)
        if (2 * i + 1 < twoE) nz += (p[2 * i + 1] != 0);
    #pragma unroll
    for (int o = 16; o; o >>= 1) nz += __shfl_xor_sync(0xffffffffu, nz, o);
    if (threadIdx.x == 0) g_is64 = (nz == 0) ? 1 : 0;
}
__global__ void convert_ei_kernel(const void* ei, int twoE) {
    int is64 = g_is64;
    const long long* p64 = (const long long*)ei;
    const int* p32 = (const int*)ei;
    for (int i = blockIdx.x * blockDim.x + threadIdx.x; i < twoE; i += gridDim.x * blockDim.x)
        g_ei[i] = is64 ? (int)p64[i] : p32[i];
}

// ---------------- small zero ----------------
__global__ void zero_small_kernel(int N) {
    int i = blockIdx.x * blockDim.x + threadIdx.x;
    if (i < N) { g_cnt[i] = 0; g_fc[i] = 0; }
    if (i < 2 * N) { g_t[i] = 0.f; g_rr[i] = 0.f; }
}

// ---------------- CSR build: hist -> scan -> fill ----------------
__global__ void hist_kernel(int E) {
    int e = blockIdx.x * blockDim.x + threadIdx.x;
    if (e < E) atomicAdd(&g_cnt[g_ei[E + e]], 1);
}

#define SCAN_T 256
#define SCAN_E 1024
__global__ void scan1_kernel(int N) {
    __shared__ int ts[SCAN_T];
    int b = blockIdx.x, t = threadIdx.x;
    int base = b * SCAN_E + t * 4;
    int v[4];
    #pragma unroll
    for (int j = 0; j < 4; j++) v[j] = (base + j < N) ? g_cnt[base + j] : 0;
    int s = v[0] + v[1] + v[2] + v[3];
    ts[t] = s;
    __syncthreads();
    for (int o = 1; o < SCAN_T; o <<= 1) {
        int xv = (t >= o) ? ts[t - o] : 0;
        __syncthreads();
        ts[t] += xv;
        __syncthreads();
    }
    if (t == SCAN_T - 1) g_blocksum[b] = ts[t];
    int run = ts[t] - s;   // exclusive
    #pragma unroll
    for (int j = 0; j < 4; j++) {
        if (base + j < N) g_rowstart[base + j] = run;
        run += v[j];
    }
}
__global__ void scan2_kernel(int nb) {
    __shared__ int ts[256];
    int t = threadIdx.x;
    ts[t] = (t < nb) ? g_blocksum[t] : 0;
    __syncthreads();
    int s = ts[t];
    for (int o = 1; o < 256; o <<= 1) {
        int xv = (t >= o) ? ts[t - o] : 0;
        __syncthreads();
        ts[t] += xv;
        __syncthreads();
    }
    g_blocksum[t] = ts[t] - s;   // exclusive
}
__global__ void scan3_kernel(int N, int E) {
    int i = blockIdx.x * blockDim.x + threadIdx.x;
    if (i < N) g_rowstart[i] += g_blocksum[i / SCAN_E];
    if (i == 0) g_rowstart[N] = E;
}
__global__ void fill_kernel(int E) {
    int e = blockIdx.x * blockDim.x + threadIdx.x;
    if (e >= E) return;
    int s = g_ei[e], d = g_ei[E + e];
    int pos = g_rowstart[d] + atomicAdd(&g_fc[d], 1);
    g_csr[pos] = s;
}

// ---------------- layer-1 aggregation: warp per node, no float atomics ----------------
__global__ void aggregate_kernel(const float* __restrict__ x, int N) {
    int warp = (blockIdx.x * blockDim.x + threadIdx.x) >> 5;
    int lane = threadIdx.x & 31;
    if (warp >= N) return;
    int start = g_rowstart[warp], end = g_rowstart[warp + 1];
    float acc[6] = {0.f, 0.f, 0.f, 0.f, 0.f, 0.f};
    for (int j = start; j < end; j++) {
        int s = g_csr[j];
        const float* xs = x + (size_t)s * F_IN_;
        #pragma unroll
        for (int m = 0; m < 6; m++) {
            int k = lane + 32 * m;
            if (k < F_IN_) acc[m] += xs[k];
        }
    }
    float inv = 1.0f / fmaxf((float)(end - start), 1.0f);
    float* ar = g_agg + (size_t)warp * APAD;
    #pragma unroll
    for (int m = 0; m < 6; m++) {
        int k = lane + 32 * m;
        if (k < F_IN_) ar[k] = acc[m] * inv;
    }
    if (lane == 0) g_deg[warp] = inv;
}

// ---------------- B hi/lo split prep ----------------
__global__ void prep_B_kernel(const float* __restrict__ w1l, const float* __restrict__ w1r) {
    int u = blockIdx.x * blockDim.x + threadIdx.x;
    if (u >= HID_ * (KPAD / 8)) return;
    int n = u / (KPAD / 8);
    int kb = (u % (KPAD / 8)) * 8;
    __align__(16) __nv_bfloat16 hi[8], lo[8];
    #pragma unroll
    for (int j = 0; j < 8; j++) {
        int k = kb + j;
        float v = 0.f;
        if (k < F_IN_)      v = w1l[k * HID_ + n];
        else if (k < KTOT)  v = w1r[(k - F_IN_) * HID_ + n];
        __nv_bfloat16 h = __float2bfloat16(v);
        hi[j] = h;
        lo[j] = __float2bfloat16(v - __bfloat162float(h));
    }
    *(uint4*)(g_Bhi + (size_t)n * KPAD + kb) = *(const uint4*)hi;
    *(uint4*)(g_Blo + (size_t)n * KPAD + kb) = *(const uint4*)lo;
}

// ---------------- mma.sync GEMM (128x256 tile) + in-kernel A split + fused proj2 ----------------
#define ROWB   80
#define SA_SZ  (128 * ROWB)           // 10240
#define SB_SZ  (256 * ROWB)           // 20480
#define OFF_AS(st) ((st) * 2 * SA_SZ)             // [Ahi|Alo] per stage
#define OFF_BS(st) (4 * SA_SZ + (st) * 2 * SB_SZ) // [Bhi|Blo] per stage
#define OFF_TAB    (4 * SA_SZ + 4 * SB_SZ)        // 122880
#define SMEM_DYN   (OFF_TAB + 1024 + 2048 + 2048)

__global__ __launch_bounds__(256, 1) void gemm_tc_kernel(
    const float* __restrict__ x, const float* __restrict__ b1,
    const float* __restrict__ w2l, const float* __restrict__ w2r, int N)
{
    extern __shared__ __align__(16) char sm[];
    uint32_t sb = smem_u32(sm);
    float* b1s  = (float*)(sm + OFF_TAB);
    float* w2ls = (float*)(sm + OFF_TAB + 1024);
    float* w2rs = (float*)(sm + OFF_TAB + 1024 + 2048);

    const int tid  = threadIdx.x;
    const int wid  = tid >> 5;
    const int lane = tid & 31;
    const int wm   = wid >> 2;          // 0..1
    const int wn   = wid & 3;           // 0..3
    const size_t rowbase = (size_t)blockIdx.x * 128;

    for (int i = tid; i < HID_; i += 256) b1s[i] = b1[i];
    for (int i = tid; i < HID_ * 2; i += 256) { w2ls[i] = w2l[i]; w2rs[i] = w2r[i]; }

    float acc[4][8][4];
    #pragma unroll
    for (int a = 0; a < 4; a++)
        #pragma unroll
        for (int b = 0; b < 8; b++)
            #pragma unroll
            for (int c = 0; c < 4; c++) acc[a][b][c] = 0.f;

    // --- A loader: warp wid owns rows [16*wid,16*wid+16); lane handles 2 consecutive k
    //     for 8 rows (row parity = lane>>4). Packs 2 bf16 per 32-bit STS.
    const int kp   = (lane & 15) * 2;   // k-pair base within chunk
    const int rpar = lane >> 4;         // row parity

    auto load_A_regs = [&](int kt, float2* v) {
        int k = kt * BK + kp;
        #pragma unroll
        for (int i = 0; i < 8; i++) {
            size_t row = rowbase + wid * 16 + i * 2 + rpar;
            float v0 = 0.f, v1 = 0.f;
            if (row < (size_t)N) {
                if (k < F_IN_)          v0 = g_agg[row * APAD + k];
                else if (k < KTOT)      v0 = x[row * F_IN_ + (k - F_IN_)];
                int k1 = k + 1;
                if (k1 < F_IN_)         v1 = g_agg[row * APAD + k1];
                else if (k1 < KTOT)     v1 = x[row * F_IN_ + (k1 - F_IN_)];
            }
            v[i] = make_float2(v0, v1);
        }
    };
    auto store_A = [&](int buf, const float2* v) {
        char* basep = sm + OFF_AS(buf);
        #pragma unroll
        for (int i = 0; i < 8; i++) {
            int rl = wid * 16 + i * 2 + rpar;
            __nv_bfloat16 h0 = __float2bfloat16(v[i].x);
            __nv_bfloat16 h1 = __float2bfloat16(v[i].y);
            __nv_bfloat16 l0 = __float2bfloat16(v[i].x - __bfloat162float(h0));
            __nv_bfloat16 l1 = __float2bfloat16(v[i].y - __bfloat162float(h1));
            uint32_t hp = ((uint32_t)*(uint16_t*)&h1 << 16) | *(uint16_t*)&h0;
            uint32_t lp = ((uint32_t)*(uint16_t*)&l1 << 16) | *(uint16_t*)&l0;
            *(uint32_t*)(basep + rl * ROWB + kp * 2) = hp;
            *(uint32_t*)(basep + SA_SZ + rl * ROWB + kp * 2) = lp;
        }
    };
    auto load_B = [&](int kt, int buf) {
        uint32_t sbuf = sb + OFF_BS(buf);
        #pragma unroll
        for (int j = 0; j < 4; j++) {
            int cid = tid + 256 * j;         // 0..1023
            int r = cid >> 2, u = cid & 3;
            uint32_t so = sbuf + r * ROWB + u * 16;
            size_t g = (size_t)r * KPAD + kt * BK + u * 8;
            CP16(so,         g_Bhi + g, 1);
            CP16(so + SB_SZ, g_Blo + g, 1);
        }
        CP_COMMIT();
    };

    float2 vreg[8];
    load_A_regs(0, vreg);
    load_B(0, 0);

    for (int kt = 0; kt < NITER; kt++) {
        int buf = kt & 1;
        store_A(buf, vreg);
        if (kt + 1 < NITER) {
            load_A_regs(kt + 1, vreg);
            load_B(kt + 1, buf ^ 1);
            CP_WAIT(1);
        } else {
            CP_WAIT(0);
        }
        __syncthreads();

        uint32_t sA = sb + OFF_AS(buf);
        uint32_t sB = sb + OFF_BS(buf);
        #pragma unroll
        for (int ks = 0; ks < 2; ks++) {
            uint32_t bh[4][4], bl[4][4];
            #pragma unroll
            for (int nf = 0; nf < 4; nf++) {
                int brow  = wn * 64 + nf * 16 + (lane & 7) + ((lane >> 4) << 3);
                int bunit = ks * 2 + ((lane >> 3) & 1);
                uint32_t ab = sB + brow * ROWB + bunit * 16;
                ldsm4(bh[nf][0], bh[nf][1], bh[nf][2], bh[nf][3], ab);
                ldsm4(bl[nf][0], bl[nf][1], bl[nf][2], bl[nf][3], ab + SB_SZ);
            }
            #pragma unroll
            for (int mf = 0; mf < 4; mf++) {
                int arow  = wm * 64 + mf * 16 + (lane & 15);
                int aunit = ks * 2 + (lane >> 4);
                uint32_t aa = sA + arow * ROWB + aunit * 16;
                uint32_t ah0, ah1, ah2, ah3, al0, al1, al2, al3;
                ldsm4(ah0, ah1, ah2, ah3, aa);
                ldsm4(al0, al1, al2, al3, aa + SA_SZ);
                // pass-major: 8 independent accumulators between reuses of any acc
                #pragma unroll
                for (int nf8 = 0; nf8 < 8; nf8++) {
                    int nf = nf8 >> 1, hf = nf8 & 1;
                    MMA16816(acc[mf][nf8], ah0, ah1, ah2, ah3,
                             bh[nf][hf * 2], bh[nf][hf * 2 + 1]);
                }
                #pragma unroll
                for (int nf8 = 0; nf8 < 8; nf8++) {
                    int nf = nf8 >> 1, hf = nf8 & 1;
                    MMA16816(acc[mf][nf8], ah0, ah1, ah2, ah3,
                             bl[nf][hf * 2], bl[nf][hf * 2 + 1]);
                }
                #pragma unroll
                for (int nf8 = 0; nf8 < 8; nf8++) {
                    int nf = nf8 >> 1, hf = nf8 & 1;
                    MMA16816(acc[mf][nf8], al0, al1, al2, al3,
                             bh[nf][hf * 2], bh[nf][hf * 2 + 1]);
                }
            }
        }
        __syncthreads();
    }

    // ---- fused epilogue: relu(acc+b1) then partial dot with w2l/w2r ----
    float pt0[8], pt1[8], pr0[8], pr1[8];
    #pragma unroll
    for (int i = 0; i < 8; i++) { pt0[i] = pt1[i] = pr0[i] = pr1[i] = 0.f; }

    #pragma unroll
    for (int mf = 0; mf < 4; mf++) {
        #pragma unroll
        for (int nf8 = 0; nf8 < 8; nf8++) {
            #pragma unroll
            for (int j = 0; j < 4; j++) {
                int colL = wn * 64 + nf8 * 8 + 2 * (lane & 3) + (j & 1);
                int i8 = mf * 2 + (j >> 1);
                float h = fmaxf(acc[mf][nf8][j] + b1s[colL], 0.f);
                pt0[i8] += h * w2ls[colL * 2];
                pt1[i8] += h * w2ls[colL * 2 + 1];
                pr0[i8] += h * w2rs[colL * 2];
                pr1[i8] += h * w2rs[colL * 2 + 1];
            }
        }
    }
    #pragma unroll
    for (int i = 0; i < 8; i++) {
        #pragma unroll
        for (int o = 1; o <= 2; o <<= 1) {
            pt0[i] += __shfl_xor_sync(0xffffffffu, pt0[i], o);
            pt1[i] += __shfl_xor_sync(0xffffffffu, pt1[i], o);
            pr0[i] += __shfl_xor_sync(0xffffffffu, pr0[i], o);
            pr1[i] += __shfl_xor_sync(0xffffffffu, pr1[i], o);
        }
        if ((lane & 3) == 0) {
            size_t row = rowbase + wm * 64 + (i >> 1) * 16 + (lane >> 2) + (i & 1) * 8;
            if (row < (size_t)N) {
                asm volatile("red.global.add.v2.f32 [%0], {%1, %2};"
                             :: "l"(&g_t[row * 2]), "f"(pt0[i]), "f"(pt1[i]) : "memory");
                asm volatile("red.global.add.v2.f32 [%0], {%1, %2};"
                             :: "l"(&g_rr[row * 2]), "f"(pr0[i]), "f"(pr1[i]) : "memory");
            }
        }
    }
}

// ---------------- layer-2 gather (CSR) fused with finalize ----------------
__global__ void gather2_kernel(float* __restrict__ out, const float* __restrict__ b2, int N) {
    int warp = (blockIdx.x * blockDim.x + threadIdx.x) >> 5;
    int lane = threadIdx.x & 31;
    if (warp >= N) return;
    int start = g_rowstart[warp], end = g_rowstart[warp + 1];
    float s0 = 0.f, s1 = 0.f;
    for (int j = start + lane; j < end; j += 32) {
        int s = g_csr[j];
        s0 += g_t[s * 2];
        s1 += g_t[s * 2 + 1];
    }
    #pragma unroll
    for (int o = 16; o; o >>= 1) {
        s0 += __shfl_xor_sync(0xffffffffu, s0, o);
        s1 += __shfl_xor_sync(0xffffffffu, s1, o);
    }
    if (lane == 0) {
        float inv = g_deg[warp];
        out[warp * 2]     = s0 * inv + g_rr[warp * 2]     + __ldg(&b2[0]);
        out[warp * 2 + 1] = s1 * inv + g_rr[warp * 2 + 1] + __ldg(&b2[1]);
    }
}

// ---------------- edge_index passthrough ----------------
__global__ void ei_out_f32_kernel(float* out, int twoE) {
    int i = blockIdx.x * blockDim.x + threadIdx.x;
    if (i < twoE) out[i] = (float)g_ei[i];
}
__global__ void ei_out_i64_kernel(long long* out, int twoE) {
    int i = blockIdx.x * blockDim.x + threadIdx.x;
    if (i < twoE) out[i] = (long long)g_ei[i];
}

// ---------------- launch ----------------
extern "C" void kernel_launch(void* const* d_in, const int* in_sizes, int n_in,
                              void* d_out, int out_size) {
    const float* x   = (const float*)d_in[0];
    const void*  ei  = d_in[1];
    const float* w1l = (const float*)d_in[2];
    const float* w1r = (const float*)d_in[3];
    const float* b1  = (const float*)d_in[4];
    const float* w2l = (const float*)d_in[5];
    const float* w2r = (const float*)d_in[6];
    const float* b2  = (const float*)d_in[7];

    int N = in_sizes[0] / F_IN_;
    int twoE = in_sizes[1];
    int E = twoE / 2;
    float* out = (float*)d_out;

    cudaFuncSetAttribute(gemm_tc_kernel, cudaFuncAttributeMaxDynamicSharedMemorySize, SMEM_DYN);

    detect_kernel<<<1, 32>>>(ei, twoE);
    convert_ei_kernel<<<1024, 256>>>(ei, twoE);
    zero_small_kernel<<<(2 * N + 255) / 256, 256>>>(N);
    hist_kernel<<<(E + 255) / 256, 256>>>(E);
    int nsb = (N + SCAN_E - 1) / SCAN_E;
    scan1_kernel<<<nsb, SCAN_T>>>(N);
    scan2_kernel<<<1, 256>>>(nsb);
    scan3_kernel<<<(N + 255) / 256, 256>>>(N, E);
    fill_kernel<<<(E + 255) / 256, 256>>>(E);
    aggregate_kernel<<<(N * 32 + 255) / 256, 256>>>(x, N);
    prep_B_kernel<<<(HID_ * (KPAD / 8) + 255) / 256, 256>>>(w1l, w1r);
    gemm_tc_kernel<<<(N + 127) / 128, 256, SMEM_DYN>>>(x, b1, w2l, w2r, N);
    gather2_kernel<<<(N * 32 + 255) / 256, 256>>>(out, b2, N);

    long long rem = (long long)out_size - (long long)2 * N;
    if (rem >= (long long)twoE) {
        if (rem >= 2LL * twoE)
            ei_out_i64_kernel<<<(twoE + 255) / 256, 256>>>((long long*)(out + (size_t)2 * N), twoE);
        else
            ei_out_f32_kernel<<<(twoE + 255) / 256, 256>>>(out + (size_t)2 * N, twoE);
    }
}

// round 6
// speedup vs baseline: 1.3314x; 1.3314x over previous
#include <cuda_runtime.h>
#include <cuda_bf16.h>
#include <cstdint>

// ---------------- problem constants ----------------
#define MAXN   200000
#define MAXE   500000
#define F_IN_  165
#define HID_   256
#define KTOT   330
#define APAD   192            // fp32 agg row stride
#define KPAD   352            // padded K (11 chunks of 32)
#define BK     32
#define NITER  (KPAD / BK)    // 11

// ---------------- device scratch ----------------
__device__ __align__(16) float g_agg[(size_t)MAXN * APAD];   // mean-agg (invd folded)
__device__ float g_deg[MAXN];                                // stores 1/max(deg,1)
__device__ __align__(16) float g_t  [MAXN * 2];
__device__ __align__(16) float g_rr [MAXN * 2];
__device__ __align__(16) __nv_bfloat16 g_Bhi[HID_ * KPAD];
__device__ __align__(16) __nv_bfloat16 g_Blo[HID_ * KPAD];
__device__ int g_ei[2 * MAXE];
__device__ int g_is64;
// CSR build
__device__ int g_cnt[MAXN];
__device__ int g_fc[MAXN];
__device__ int g_rowstart[MAXN + 1];
__device__ int g_blocksum[256];
__device__ int g_csr[MAXE];

// ---------------- PTX helpers (base-ISA; tcgen05 is sm_103a-gated, unusable here) ----------------
__device__ __forceinline__ uint32_t smem_u32(const void* p) {
    uint32_t a;
    asm("{ .reg .u64 t; cvta.to.shared.u64 t, %1; cvt.u32.u64 %0, t; }" : "=r"(a) : "l"(p));
    return a;
}
__device__ __forceinline__ void ldsm4(uint32_t& r0, uint32_t& r1, uint32_t& r2, uint32_t& r3,
                                      uint32_t addr) {
    asm volatile("ldmatrix.sync.aligned.m8n8.x4.shared.b16 {%0,%1,%2,%3}, [%4];"
                 : "=r"(r0), "=r"(r1), "=r"(r2), "=r"(r3) : "r"(addr));
}
// volatile: pins program order (we control scheduling explicitly; avoids spill pathology)
#define MMA16816(c, a0, a1, a2, a3, b0, b1)                                            \
    asm volatile(                                                                      \
        "mma.sync.aligned.m16n8k16.row.col.f32.bf16.bf16.f32 "                         \
        "{%0,%1,%2,%3}, {%4,%5,%6,%7}, {%8,%9}, {%0,%1,%2,%3};"                        \
        : "+f"((c)[0]), "+f"((c)[1]), "+f"((c)[2]), "+f"((c)[3])                       \
        : "r"(a0), "r"(a1), "r"(a2), "r"(a3), "r"(b0), "r"(b1))
#define CP16(dst, src, pred)                                                           \
    asm volatile("cp.async.cg.shared.global [%0], [%1], 16, %2;"                       \
                 :: "r"(dst), "l"(src), "r"((pred) ? 16 : 0) : "memory")
#define CP_COMMIT() asm volatile("cp.async.commit_group;" ::: "memory")
#define CP_WAIT(n)  asm volatile("cp.async.wait_group %0;" :: "n"(n) : "memory")

// ---------------- edge index canon ----------------
__global__ void detect_kernel(const void* ei, int twoE) {
    const int* p = (const int*)ei;
    int nz = 0;
    for (int i = threadIdx.x; i < 256; i += 32)
        if (2 * i + 1 < twoE) nz += (p[2 * i + 1] != 0);
    #pragma unroll
    for (int o = 16; o; o >>= 1) nz += __shfl_xor_sync(0xffffffffu, nz, o);
    if (threadIdx.x == 0) g_is64 = (nz == 0) ? 1 : 0;
}
__global__ void convert_ei_kernel(const void* ei, int twoE) {
    int is64 = g_is64;
    const long long* p64 = (const long long*)ei;
    const int* p32 = (const int*)ei;
    for (int i = blockIdx.x * blockDim.x + threadIdx.x; i < twoE; i += gridDim.x * blockDim.x)
        g_ei[i] = is64 ? (int)p64[i] : p32[i];
}

// ---------------- small zero ----------------
__global__ void zero_small_kernel(int N) {
    int i = blockIdx.x * blockDim.x + threadIdx.x;
    if (i < N) { g_cnt[i] = 0; g_fc[i] = 0; }
    if (i < 2 * N) { g_t[i] = 0.f; g_rr[i] = 0.f; }
}

// ---------------- CSR build: hist -> scan -> fill ----------------
__global__ void hist_kernel(int E) {
    int e = blockIdx.x * blockDim.x + threadIdx.x;
    if (e < E) atomicAdd(&g_cnt[g_ei[E + e]], 1);
}

#define SCAN_T 256
#define SCAN_E 1024
__global__ void scan1_kernel(int N) {
    __shared__ int ts[SCAN_T];
    int b = blockIdx.x, t = threadIdx.x;
    int base = b * SCAN_E + t * 4;
    int v[4];
    #pragma unroll
    for (int j = 0; j < 4; j++) v[j] = (base + j < N) ? g_cnt[base + j] : 0;
    int s = v[0] + v[1] + v[2] + v[3];
    ts[t] = s;
    __syncthreads();
    for (int o = 1; o < SCAN_T; o <<= 1) {
        int xv = (t >= o) ? ts[t - o] : 0;
        __syncthreads();
        ts[t] += xv;
        __syncthreads();
    }
    if (t == SCAN_T - 1) g_blocksum[b] = ts[t];
    int run = ts[t] - s;   // exclusive
    #pragma unroll
    for (int j = 0; j < 4; j++) {
        if (base + j < N) g_rowstart[base + j] = run;
        run += v[j];
    }
}
__global__ void scan2_kernel(int nb) {
    __shared__ int ts[256];
    int t = threadIdx.x;
    ts[t] = (t < nb) ? g_blocksum[t] : 0;
    __syncthreads();
    int s = ts[t];
    for (int o = 1; o < 256; o <<= 1) {
        int xv = (t >= o) ? ts[t - o] : 0;
        __syncthreads();
        ts[t] += xv;
        __syncthreads();
    }
    g_blocksum[t] = ts[t] - s;   // exclusive
}
__global__ void scan3_kernel(int N, int E) {
    int i = blockIdx.x * blockDim.x + threadIdx.x;
    if (i < N) g_rowstart[i] += g_blocksum[i / SCAN_E];
    if (i == 0) g_rowstart[N] = E;
}
__global__ void fill_kernel(int E) {
    int e = blockIdx.x * blockDim.x + threadIdx.x;
    if (e >= E) return;
    int s = g_ei[e], d = g_ei[E + e];
    int pos = g_rowstart[d] + atomicAdd(&g_fc[d], 1);
    g_csr[pos] = s;
}

// ---------------- layer-1 aggregation: warp per node, no float atomics ----------------
__global__ void aggregate_kernel(const float* __restrict__ x, int N) {
    int warp = (blockIdx.x * blockDim.x + threadIdx.x) >> 5;
    int lane = threadIdx.x & 31;
    if (warp >= N) return;
    int start = g_rowstart[warp], end = g_rowstart[warp + 1];
    float acc[6] = {0.f, 0.f, 0.f, 0.f, 0.f, 0.f};
    for (int j = start; j < end; j++) {
        int s = g_csr[j];
        const float* xs = x + (size_t)s * F_IN_;
        #pragma unroll
        for (int m = 0; m < 6; m++) {
            int k = lane + 32 * m;
            if (k < F_IN_) acc[m] += xs[k];
        }
    }
    float inv = 1.0f / fmaxf((float)(end - start), 1.0f);
    float* ar = g_agg + (size_t)warp * APAD;
    #pragma unroll
    for (int m = 0; m < 6; m++) {
        int k = lane + 32 * m;
        if (k < F_IN_) ar[k] = acc[m] * inv;
    }
    if (lane == 0) g_deg[warp] = inv;
}

// ---------------- B hi/lo split prep ----------------
__global__ void prep_B_kernel(const float* __restrict__ w1l, const float* __restrict__ w1r) {
    int u = blockIdx.x * blockDim.x + threadIdx.x;
    if (u >= HID_ * (KPAD / 8)) return;
    int n = u / (KPAD / 8);
    int kb = (u % (KPAD / 8)) * 8;
    __align__(16) __nv_bfloat16 hi[8], lo[8];
    #pragma unroll
    for (int j = 0; j < 8; j++) {
        int k = kb + j;
        float v = 0.f;
        if (k < F_IN_)      v = w1l[k * HID_ + n];
        else if (k < KTOT)  v = w1r[(k - F_IN_) * HID_ + n];
        __nv_bfloat16 h = __float2bfloat16(v);
        hi[j] = h;
        lo[j] = __float2bfloat16(v - __bfloat162float(h));
    }
    *(uint4*)(g_Bhi + (size_t)n * KPAD + kb) = *(const uint4*)hi;
    *(uint4*)(g_Blo + (size_t)n * KPAD + kb) = *(const uint4*)lo;
}

// ---------------- mma.sync GEMM (128x256 tile) + in-kernel A split + fused proj2 ----------------
#define ROWB   80
#define SA_SZ  (128 * ROWB)           // 10240
#define SB_SZ  (256 * ROWB)           // 20480
#define OFF_AS(st) ((st) * 2 * SA_SZ)             // [Ahi|Alo] per stage
#define OFF_BS(st) (4 * SA_SZ + (st) * 2 * SB_SZ) // [Bhi|Blo] per stage
#define OFF_TAB    (4 * SA_SZ + 4 * SB_SZ)        // 122880
#define SMEM_DYN   (OFF_TAB + 1024 + 2048 + 2048)

__global__ __launch_bounds__(256, 1) void gemm_tc_kernel(
    const float* __restrict__ x, const float* __restrict__ b1,
    const float* __restrict__ w2l, const float* __restrict__ w2r, int N)
{
    extern __shared__ __align__(16) char sm[];
    uint32_t sb = smem_u32(sm);
    float* b1s  = (float*)(sm + OFF_TAB);
    float* w2ls = (float*)(sm + OFF_TAB + 1024);
    float* w2rs = (float*)(sm + OFF_TAB + 1024 + 2048);

    const int tid  = threadIdx.x;
    const int wid  = tid >> 5;
    const int lane = tid & 31;
    const int wm   = wid >> 2;          // 0..1
    const int wn   = wid & 3;           // 0..3
    const size_t rowbase = (size_t)blockIdx.x * 128;

    for (int i = tid; i < HID_; i += 256) b1s[i] = b1[i];
    for (int i = tid; i < HID_ * 2; i += 256) { w2ls[i] = w2l[i]; w2rs[i] = w2r[i]; }

    float acc[4][8][4];
    #pragma unroll
    for (int a = 0; a < 4; a++)
        #pragma unroll
        for (int b = 0; b < 8; b++)
            #pragma unroll
            for (int c = 0; c < 4; c++) acc[a][b][c] = 0.f;

    // --- A register loader: warp wid handles rows [16*wid, 16*wid+16), lane = k-in-chunk ---
    auto load_A_regs = [&](int kt, float* v) {
        int k = kt * BK + lane;
        int cls = (k < F_IN_) ? 0 : ((k < KTOT) ? 1 : 2);
        #pragma unroll
        for (int r = 0; r < 16; r++) {
            size_t row = rowbase + wid * 16 + r;
            float val = 0.f;
            if (row < (size_t)N) {
                if (cls == 0)      val = g_agg[row * APAD + k];
                else if (cls == 1) val = x[row * F_IN_ + (k - F_IN_)];
            }
            v[r] = val;
        }
    };
    auto store_A = [&](int buf, const float* v) {
        char* basep = sm + OFF_AS(buf);
        #pragma unroll
        for (int r = 0; r < 16; r++) {
            int rl = wid * 16 + r;
            float val = v[r];
            __nv_bfloat16 h = __float2bfloat16(val);
            __nv_bfloat16 l = __float2bfloat16(val - __bfloat162float(h));
            *(__nv_bfloat16*)(basep + rl * ROWB + lane * 2) = h;
            *(__nv_bfloat16*)(basep + SA_SZ + rl * ROWB + lane * 2) = l;
        }
    };
    auto load_B = [&](int kt, int buf) {
        uint32_t sbuf = sb + OFF_BS(buf);
        #pragma unroll
        for (int j = 0; j < 4; j++) {
            int cid = tid + 256 * j;         // 0..1023
            int r = cid >> 2, u = cid & 3;
            uint32_t so = sbuf + r * ROWB + u * 16;
            size_t g = (size_t)r * KPAD + kt * BK + u * 8;
            CP16(so,         g_Bhi + g, 1);
            CP16(so + SB_SZ, g_Blo + g, 1);
        }
        CP_COMMIT();
    };

    float vreg[16];
    load_A_regs(0, vreg);
    load_B(0, 0);

    for (int kt = 0; kt < NITER; kt++) {
        int buf = kt & 1;
        store_A(buf, vreg);
        if (kt + 1 < NITER) {
            load_A_regs(kt + 1, vreg);
            load_B(kt + 1, buf ^ 1);
            CP_WAIT(1);
        } else {
            CP_WAIT(0);
        }
        __syncthreads();

        uint32_t sA = sb + OFF_AS(buf);
        uint32_t sB = sb + OFF_BS(buf);
        #pragma unroll
        for (int ks = 0; ks < 2; ks++) {
            uint32_t bh[4][4], bl[4][4];
            #pragma unroll
            for (int nf = 0; nf < 4; nf++) {
                int brow  = wn * 64 + nf * 16 + (lane & 7) + ((lane >> 4) << 3);
                int bunit = ks * 2 + ((lane >> 3) & 1);
                uint32_t ab = sB + brow * ROWB + bunit * 16;
                ldsm4(bh[nf][0], bh[nf][1], bh[nf][2], bh[nf][3], ab);
                ldsm4(bl[nf][0], bl[nf][1], bl[nf][2], bl[nf][3], ab + SB_SZ);
            }
            #pragma unroll
            for (int mf = 0; mf < 4; mf++) {
                int arow  = wm * 64 + mf * 16 + (lane & 15);
                int aunit = ks * 2 + (lane >> 4);
                uint32_t aa = sA + arow * ROWB + aunit * 16;
                uint32_t ah0, ah1, ah2, ah3, al0, al1, al2, al3;
                ldsm4(ah0, ah1, ah2, ah3, aa);
                ldsm4(al0, al1, al2, al3, aa + SA_SZ);
                // pass-major, volatile-pinned: 8 independent accumulators between
                // any two MMAs that share an accumulator (covers HMMA RAW latency).
                #pragma unroll
                for (int nf8 = 0; nf8 < 8; nf8++) {
                    int nf = nf8 >> 1, hf = nf8 & 1;
                    MMA16816(acc[mf][nf8], ah0, ah1, ah2, ah3,
                             bh[nf][hf * 2], bh[nf][hf * 2 + 1]);
                }
                #pragma unroll
                for (int nf8 = 0; nf8 < 8; nf8++) {
                    int nf = nf8 >> 1, hf = nf8 & 1;
                    MMA16816(acc[mf][nf8], ah0, ah1, ah2, ah3,
                             bl[nf][hf * 2], bl[nf][hf * 2 + 1]);
                }
                #pragma unroll
                for (int nf8 = 0; nf8 < 8; nf8++) {
                    int nf = nf8 >> 1, hf = nf8 & 1;
                    MMA16816(acc[mf][nf8], al0, al1, al2, al3,
                             bh[nf][hf * 2], bh[nf][hf * 2 + 1]);
                }
            }
        }
        __syncthreads();
    }

    // ---- fused epilogue: relu(acc+b1) then partial dot with w2l/w2r ----
    float pt0[8], pt1[8], pr0[8], pr1[8];
    #pragma unroll
    for (int i = 0; i < 8; i++) { pt0[i] = pt1[i] = pr0[i] = pr1[i] = 0.f; }

    #pragma unroll
    for (int mf = 0; mf < 4; mf++) {
        #pragma unroll
        for (int nf8 = 0; nf8 < 8; nf8++) {
            #pragma unroll
            for (int j = 0; j < 4; j++) {
                int colL = wn * 64 + nf8 * 8 + 2 * (lane & 3) + (j & 1);
                int i8 = mf * 2 + (j >> 1);
                float h = fmaxf(acc[mf][nf8][j] + b1s[colL], 0.f);
                pt0[i8] += h * w2ls[colL * 2];
                pt1[i8] += h * w2ls[colL * 2 + 1];
                pr0[i8] += h * w2rs[colL * 2];
                pr1[i8] += h * w2rs[colL * 2 + 1];
            }
        }
    }
    #pragma unroll
    for (int i = 0; i < 8; i++) {
        #pragma unroll
        for (int o = 1; o <= 2; o <<= 1) {
            pt0[i] += __shfl_xor_sync(0xffffffffu, pt0[i], o);
            pt1[i] += __shfl_xor_sync(0xffffffffu, pt1[i], o);
            pr0[i] += __shfl_xor_sync(0xffffffffu, pr0[i], o);
            pr1[i] += __shfl_xor_sync(0xffffffffu, pr1[i], o);
        }
        if ((lane & 3) == 0) {
            size_t row = rowbase + wm * 64 + (i >> 1) * 16 + (lane >> 2) + (i & 1) * 8;
            if (row < (size_t)N) {
                asm volatile("red.global.add.v2.f32 [%0], {%1, %2};"
                             :: "l"(&g_t[row * 2]), "f"(pt0[i]), "f"(pt1[i]) : "memory");
                asm volatile("red.global.add.v2.f32 [%0], {%1, %2};"
                             :: "l"(&g_rr[row * 2]), "f"(pr0[i]), "f"(pr1[i]) : "memory");
            }
        }
    }
}

// ---------------- layer-2 gather (CSR) fused with finalize ----------------
__global__ void gather2_kernel(float* __restrict__ out, const float* __restrict__ b2, int N) {
    int warp = (blockIdx.x * blockDim.x + threadIdx.x) >> 5;
    int lane = threadIdx.x & 31;
    if (warp >= N) return;
    int start = g_rowstart[warp], end = g_rowstart[warp + 1];
    float s0 = 0.f, s1 = 0.f;
    for (int j = start + lane; j < end; j += 32) {
        int s = g_csr[j];
        s0 += g_t[s * 2];
        s1 += g_t[s * 2 + 1];
    }
    #pragma unroll
    for (int o = 16; o; o >>= 1) {
        s0 += __shfl_xor_sync(0xffffffffu, s0, o);
        s1 += __shfl_xor_sync(0xffffffffu, s1, o);
    }
    if (lane == 0) {
        float inv = g_deg[warp];
        out[warp * 2]     = s0 * inv + g_rr[warp * 2]     + __ldg(&b2[0]);
        out[warp * 2 + 1] = s1 * inv + g_rr[warp * 2 + 1] + __ldg(&b2[1]);
    }
}

// ---------------- edge_index passthrough ----------------
__global__ void ei_out_f32_kernel(float* out, int twoE) {
    int i = blockIdx.x * blockDim.x + threadIdx.x;
    if (i < twoE) out[i] = (float)g_ei[i];
}
__global__ void ei_out_i64_kernel(long long* out, int twoE) {
    int i = blockIdx.x * blockDim.x + threadIdx.x;
    if (i < twoE) out[i] = (long long)g_ei[i];
}

// ---------------- launch ----------------
extern "C" void kernel_launch(void* const* d_in, const int* in_sizes, int n_in,
                              void* d_out, int out_size) {
    const float* x   = (const float*)d_in[0];
    const void*  ei  = d_in[1];
    const float* w1l = (const float*)d_in[2];
    const float* w1r = (const float*)d_in[3];
    const float* b1  = (const float*)d_in[4];
    const float* w2l = (const float*)d_in[5];
    const float* w2r = (const float*)d_in[6];
    const float* b2  = (const float*)d_in[7];

    int N = in_sizes[0] / F_IN_;
    int twoE = in_sizes[1];
    int E = twoE / 2;
    float* out = (float*)d_out;

    cudaFuncSetAttribute(gemm_tc_kernel, cudaFuncAttributeMaxDynamicSharedMemorySize, SMEM_DYN);

    detect_kernel<<<1, 32>>>(ei, twoE);
    convert_ei_kernel<<<1024, 256>>>(ei, twoE);
    zero_small_kernel<<<(2 * N + 255) / 256, 256>>>(N);
    hist_kernel<<<(E + 255) / 256, 256>>>(E);
    int nsb = (N + SCAN_E - 1) / SCAN_E;
    scan1_kernel<<<nsb, SCAN_T>>>(N);
    scan2_kernel<<<1, 256>>>(nsb);
    scan3_kernel<<<(N + 255) / 256, 256>>>(N, E);
    fill_kernel<<<(E + 255) / 256, 256>>>(E);
    aggregate_kernel<<<(N * 32 + 255) / 256, 256>>>(x, N);
    prep_B_kernel<<<(HID_ * (KPAD / 8) + 255) / 256, 256>>>(w1l, w1r);
    gemm_tc_kernel<<<(N + 127) / 128, 256, SMEM_DYN>>>(x, b1, w2l, w2r, N);
    gather2_kernel<<<(N * 32 + 255) / 256, 256>>>(out, b2, N);

    long long rem = (long long)out_size - (long long)2 * N;
    if (rem >= (long long)twoE) {
        if (rem >= 2LL * twoE)
            ei_out_i64_kernel<<<(twoE + 255) / 256, 256>>>((long long*)(out + (size_t)2 * N), twoE);
        else
            ei_out_f32_kernel<<<(twoE + 255) / 256, 256>>>(out + (size_t)2 * N, twoE);
    }
}

// round 7
// speedup vs baseline: 2.3718x; 1.7814x over previous
#include <cuda_runtime.h>
#include <cuda_fp16.h>
#include <cstdint>

// ---------------- problem constants ----------------
#define MAXN   200000
#define MAXE   500000
#define F_IN_  165
#define HID_   256
#define KTOT   330
#define KPAD   352            // padded K (11 chunks of 32)
#define BK     32
#define NITER  (KPAD / BK)    // 11

// ---------------- device scratch ----------------
__device__ float g_deg[MAXN];                                // 1/max(deg,1)
__device__ __align__(16) float g_t  [MAXN * 2];
__device__ __align__(16) float g_rr [MAXN * 2];
__device__ __align__(16) __half g_Ah[(size_t)MAXN * KPAD];   // [agg*invd | x] fp16
__device__ __align__(16) __half g_Bh[HID_ * KPAD];           // [w1_l ; w1_r] fp16 (col rows)
__device__ int g_ei[2 * MAXE];
__device__ int g_is64;
// CSR build
__device__ int g_cnt[MAXN];
__device__ int g_fc[MAXN];
__device__ int g_rowstart[MAXN + 1];
__device__ int g_blocksum[256];
__device__ int g_csr[MAXE];

// ---------------- PTX helpers (base-ISA; tcgen05 is sm_103a-gated, unusable here) ----------------
__device__ __forceinline__ uint32_t smem_u32(const void* p) {
    uint32_t a;
    asm("{ .reg .u64 t; cvta.to.shared.u64 t, %1; cvt.u32.u64 %0, t; }" : "=r"(a) : "l"(p));
    return a;
}
__device__ __forceinline__ void ldsm4(uint32_t& r0, uint32_t& r1, uint32_t& r2, uint32_t& r3,
                                      uint32_t addr) {
    asm volatile("ldmatrix.sync.aligned.m8n8.x4.shared.b16 {%0,%1,%2,%3}, [%4];"
                 : "=r"(r0), "=r"(r1), "=r"(r2), "=r"(r3) : "r"(addr));
}
#define MMA16816(c, a0, a1, a2, a3, b0, b1)                                            \
    asm volatile(                                                                      \
        "mma.sync.aligned.m16n8k16.row.col.f32.f16.f16.f32 "                           \
        "{%0,%1,%2,%3}, {%4,%5,%6,%7}, {%8,%9}, {%0,%1,%2,%3};"                        \
        : "+f"((c)[0]), "+f"((c)[1]), "+f"((c)[2]), "+f"((c)[3])                       \
        : "r"(a0), "r"(a1), "r"(a2), "r"(a3), "r"(b0), "r"(b1))
#define CP16(dst, src, pred)                                                           \
    asm volatile("cp.async.cg.shared.global [%0], [%1], 16, %2;"                       \
                 :: "r"(dst), "l"(src), "r"((pred) ? 16 : 0) : "memory")
#define CP_COMMIT() asm volatile("cp.async.commit_group;" ::: "memory")
#define CP_WAIT(n)  asm volatile("cp.async.wait_group %0;" :: "n"(n) : "memory")

// ---------------- edge index canon ----------------
__global__ void detect_kernel(const void* ei, int twoE) {
    const int* p = (const int*)ei;
    int nz = 0;
    for (int i = threadIdx.x; i < 256; i += 32)
        if (2 * i + 1 < twoE) nz += (p[2 * i + 1] != 0);
    #pragma unroll
    for (int o = 16; o; o >>= 1) nz += __shfl_xor_sync(0xffffffffu, nz, o);
    if (threadIdx.x == 0) g_is64 = (nz == 0) ? 1 : 0;
}
__global__ void convert_ei_kernel(const void* ei, int twoE) {
    int is64 = g_is64;
    const long long* p64 = (const long long*)ei;
    const int* p32 = (const int*)ei;
    for (int i = blockIdx.x * blockDim.x + threadIdx.x; i < twoE; i += gridDim.x * blockDim.x)
        g_ei[i] = is64 ? (int)p64[i] : p32[i];
}

// ---------------- small zero ----------------
__global__ void zero_small_kernel(int N) {
    int i = blockIdx.x * blockDim.x + threadIdx.x;
    if (i < N) { g_cnt[i] = 0; g_fc[i] = 0; }
    if (i < 2 * N) { g_t[i] = 0.f; g_rr[i] = 0.f; }
}

// ---------------- CSR build: hist -> scan -> fill ----------------
__global__ void hist_kernel(int E) {
    int e = blockIdx.x * blockDim.x + threadIdx.x;
    if (e < E) atomicAdd(&g_cnt[g_ei[E + e]], 1);
}

#define SCAN_T 256
#define SCAN_E 1024
__global__ void scan1_kernel(int N) {
    __shared__ int ts[SCAN_T];
    int b = blockIdx.x, t = threadIdx.x;
    int base = b * SCAN_E + t * 4;
    int v[4];
    #pragma unroll
    for (int j = 0; j < 4; j++) v[j] = (base + j < N) ? g_cnt[base + j] : 0;
    int s = v[0] + v[1] + v[2] + v[3];
    ts[t] = s;
    __syncthreads();
    for (int o = 1; o < SCAN_T; o <<= 1) {
        int xv = (t >= o) ? ts[t - o] : 0;
        __syncthreads();
        ts[t] += xv;
        __syncthreads();
    }
    if (t == SCAN_T - 1) g_blocksum[b] = ts[t];
    int run = ts[t] - s;   // exclusive
    #pragma unroll
    for (int j = 0; j < 4; j++) {
        if (base + j < N) g_rowstart[base + j] = run;
        run += v[j];
    }
}
__global__ void scan2_kernel(int nb) {
    __shared__ int ts[256];
    int t = threadIdx.x;
    ts[t] = (t < nb) ? g_blocksum[t] : 0;
    __syncthreads();
    int s = ts[t];
    for (int o = 1; o < 256; o <<= 1) {
        int xv = (t >= o) ? ts[t - o] : 0;
        __syncthreads();
        ts[t] += xv;
        __syncthreads();
    }
    g_blocksum[t] = ts[t] - s;   // exclusive
}
__global__ void scan3_kernel(int N, int E) {
    int i = blockIdx.x * blockDim.x + threadIdx.x;
    if (i < N) g_rowstart[i] += g_blocksum[i / SCAN_E];
    if (i == 0) g_rowstart[N] = E;
}
__global__ void fill_kernel(int E) {
    int e = blockIdx.x * blockDim.x + threadIdx.x;
    if (e >= E) return;
    int s = g_ei[e], d = g_ei[E + e];
    int pos = g_rowstart[d] + atomicAdd(&g_fc[d], 1);
    g_csr[pos] = s;
}

// ---------------- layer-1 aggregation + fp16 A materialization ----------------
// Writes the full GEMM A row in fp16: [mean-agg (165) | x root (165) | 0-pad (22)]
__global__ void aggregate_kernel(const float* __restrict__ x, int N) {
    int warp = (blockIdx.x * blockDim.x + threadIdx.x) >> 5;
    int lane = threadIdx.x & 31;
    if (warp >= N) return;
    int start = g_rowstart[warp], end = g_rowstart[warp + 1];
    float acc[6] = {0.f, 0.f, 0.f, 0.f, 0.f, 0.f};
    for (int j = start; j < end; j++) {
        int s = g_csr[j];
        const float* xs = x + (size_t)s * F_IN_;
        #pragma unroll
        for (int m = 0; m < 6; m++) {
            int k = lane + 32 * m;
            if (k < F_IN_) acc[m] += xs[k];
        }
    }
    float inv = 1.0f / fmaxf((float)(end - start), 1.0f);
    __half* ar = g_Ah + (size_t)warp * KPAD;
    const float* xr = x + (size_t)warp * F_IN_;
    #pragma unroll
    for (int m = 0; m < 6; m++) {
        int k = lane + 32 * m;
        if (k < F_IN_) {
            ar[k] = __float2half(acc[m] * inv);
            ar[F_IN_ + k] = __float2half(xr[k]);
        }
    }
    if (lane < KPAD - KTOT) ar[KTOT + lane] = __float2half(0.f);
    if (lane == 0) g_deg[warp] = inv;
}

// ---------------- B fp16 prep ----------------
__global__ void prep_B_kernel(const float* __restrict__ w1l, const float* __restrict__ w1r) {
    int u = blockIdx.x * blockDim.x + threadIdx.x;
    if (u >= HID_ * (KPAD / 8)) return;
    int n = u / (KPAD / 8);
    int kb = (u % (KPAD / 8)) * 8;
    __align__(16) __half h[8];
    #pragma unroll
    for (int j = 0; j < 8; j++) {
        int k = kb + j;
        float v = 0.f;
        if (k < F_IN_)      v = w1l[k * HID_ + n];
        else if (k < KTOT)  v = w1r[(k - F_IN_) * HID_ + n];
        h[j] = __float2half(v);
    }
    *(uint4*)(g_Bh + (size_t)n * KPAD + kb) = *(const uint4*)h;
}

// ---------------- single-pass fp16 mma.sync GEMM (128x256) + fused proj2 ----------------
#define ROWB   80
#define SA_SZ  (128 * ROWB)           // 10240
#define SB_SZ  (256 * ROWB)           // 20480
#define OFF_AS(st) ((st) * SA_SZ)                 // A per stage
#define OFF_BS(st) (2 * SA_SZ + (st) * SB_SZ)     // B per stage
#define OFF_TAB    (2 * SA_SZ + 2 * SB_SZ)        // 61440
#define SMEM_DYN   (OFF_TAB + 1024 + 2048 + 2048)

__global__ __launch_bounds__(256, 1) void gemm_tc_kernel(
    const float* __restrict__ b1, const float* __restrict__ w2l,
    const float* __restrict__ w2r, int N)
{
    extern __shared__ __align__(16) char sm[];
    uint32_t sb = smem_u32(sm);
    float* b1s  = (float*)(sm + OFF_TAB);
    float* w2ls = (float*)(sm + OFF_TAB + 1024);
    float* w2rs = (float*)(sm + OFF_TAB + 1024 + 2048);

    const int tid  = threadIdx.x;
    const int wid  = tid >> 5;
    const int lane = tid & 31;
    const int wm   = wid >> 2;          // 0..1
    const int wn   = wid & 3;           // 0..3
    const size_t rowbase = (size_t)blockIdx.x * 128;

    for (int i = tid; i < HID_; i += 256) b1s[i] = b1[i];
    for (int i = tid; i < HID_ * 2; i += 256) { w2ls[i] = w2l[i]; w2rs[i] = w2r[i]; }

    float acc[4][8][4];
    #pragma unroll
    for (int a = 0; a < 4; a++)
        #pragma unroll
        for (int b = 0; b < 8; b++)
            #pragma unroll
            for (int c = 0; c < 4; c++) acc[a][b][c] = 0.f;

    auto load_stage = [&](int kt, int buf) {
        // A: 128 rows x 4 x 16B
        #pragma unroll
        for (int j = 0; j < 2; j++) {
            int cid = tid + 256 * j;         // 0..511
            int r = cid >> 2, u = cid & 3;
            uint32_t so = sb + OFF_AS(buf) + r * ROWB + u * 16;
            size_t row = rowbase + r;
            CP16(so, g_Ah + row * KPAD + kt * BK + u * 8, row < (size_t)N);
        }
        // B: 256 rows x 4 x 16B
        #pragma unroll
        for (int j = 0; j < 4; j++) {
            int cid = tid + 256 * j;         // 0..1023
            int r = cid >> 2, u = cid & 3;
            uint32_t so = sb + OFF_BS(buf) + r * ROWB + u * 16;
            CP16(so, g_Bh + (size_t)r * KPAD + kt * BK + u * 8, 1);
        }
        CP_COMMIT();
    };

    load_stage(0, 0);

    for (int kt = 0; kt < NITER; kt++) {
        int buf = kt & 1;
        if (kt + 1 < NITER) {
            load_stage(kt + 1, buf ^ 1);
            CP_WAIT(1);
        } else {
            CP_WAIT(0);
        }
        __syncthreads();

        uint32_t sA = sb + OFF_AS(buf);
        uint32_t sB = sb + OFF_BS(buf);
        #pragma unroll
        for (int ks = 0; ks < 2; ks++) {
            uint32_t bh[4][4];
            #pragma unroll
            for (int nf = 0; nf < 4; nf++) {
                int brow  = wn * 64 + nf * 16 + (lane & 7) + ((lane >> 4) << 3);
                int bunit = ks * 2 + ((lane >> 3) & 1);
                ldsm4(bh[nf][0], bh[nf][1], bh[nf][2], bh[nf][3],
                      sB + brow * ROWB + bunit * 16);
            }
            #pragma unroll
            for (int mf = 0; mf < 4; mf++) {
                int arow  = wm * 64 + mf * 16 + (lane & 15);
                int aunit = ks * 2 + (lane >> 4);
                uint32_t ah0, ah1, ah2, ah3;
                ldsm4(ah0, ah1, ah2, ah3, sA + arow * ROWB + aunit * 16);
                #pragma unroll
                for (int nf8 = 0; nf8 < 8; nf8++) {
                    int nf = nf8 >> 1, hf = nf8 & 1;
                    MMA16816(acc[mf][nf8], ah0, ah1, ah2, ah3,
                             bh[nf][hf * 2], bh[nf][hf * 2 + 1]);
                }
            }
        }
        __syncthreads();
    }

    // ---- fused epilogue: relu(acc+b1) then partial dot with w2l/w2r ----
    float pt0[8], pt1[8], pr0[8], pr1[8];
    #pragma unroll
    for (int i = 0; i < 8; i++) { pt0[i] = pt1[i] = pr0[i] = pr1[i] = 0.f; }

    #pragma unroll
    for (int mf = 0; mf < 4; mf++) {
        #pragma unroll
        for (int nf8 = 0; nf8 < 8; nf8++) {
            #pragma unroll
            for (int j = 0; j < 4; j++) {
                int colL = wn * 64 + nf8 * 8 + 2 * (lane & 3) + (j & 1);
                int i8 = mf * 2 + (j >> 1);
                float h = fmaxf(acc[mf][nf8][j] + b1s[colL], 0.f);
                pt0[i8] += h * w2ls[colL * 2];
                pt1[i8] += h * w2ls[colL * 2 + 1];
                pr0[i8] += h * w2rs[colL * 2];
                pr1[i8] += h * w2rs[colL * 2 + 1];
            }
        }
    }
    #pragma unroll
    for (int i = 0; i < 8; i++) {
        #pragma unroll
        for (int o = 1; o <= 2; o <<= 1) {
            pt0[i] += __shfl_xor_sync(0xffffffffu, pt0[i], o);
            pt1[i] += __shfl_xor_sync(0xffffffffu, pt1[i], o);
            pr0[i] += __shfl_xor_sync(0xffffffffu, pr0[i], o);
            pr1[i] += __shfl_xor_sync(0xffffffffu, pr1[i], o);
        }
        if ((lane & 3) == 0) {
            size_t row = rowbase + wm * 64 + (i >> 1) * 16 + (lane >> 2) + (i & 1) * 8;
            if (row < (size_t)N) {
                asm volatile("red.global.add.v2.f32 [%0], {%1, %2};"
                             :: "l"(&g_t[row * 2]), "f"(pt0[i]), "f"(pt1[i]) : "memory");
                asm volatile("red.global.add.v2.f32 [%0], {%1, %2};"
                             :: "l"(&g_rr[row * 2]), "f"(pr0[i]), "f"(pr1[i]) : "memory");
            }
        }
    }
}

// ---------------- layer-2 gather (CSR) fused with finalize ----------------
__global__ void gather2_kernel(float* __restrict__ out, const float* __restrict__ b2, int N) {
    int warp = (blockIdx.x * blockDim.x + threadIdx.x) >> 5;
    int lane = threadIdx.x & 31;
    if (warp >= N) return;
    int start = g_rowstart[warp], end = g_rowstart[warp + 1];
    float s0 = 0.f, s1 = 0.f;
    for (int j = start + lane; j < end; j += 32) {
        int s = g_csr[j];
        s0 += g_t[s * 2];
        s1 += g_t[s * 2 + 1];
    }
    #pragma unroll
    for (int o = 16; o; o >>= 1) {
        s0 += __shfl_xor_sync(0xffffffffu, s0, o);
        s1 += __shfl_xor_sync(0xffffffffu, s1, o);
    }
    if (lane == 0) {
        float inv = g_deg[warp];
        out[warp * 2]     = s0 * inv + g_rr[warp * 2]     + __ldg(&b2[0]);
        out[warp * 2 + 1] = s1 * inv + g_rr[warp * 2 + 1] + __ldg(&b2[1]);
    }
}

// ---------------- edge_index passthrough ----------------
__global__ void ei_out_f32_kernel(float* out, int twoE) {
    int i = blockIdx.x * blockDim.x + threadIdx.x;
    if (i < twoE) out[i] = (float)g_ei[i];
}
__global__ void ei_out_i64_kernel(long long* out, int twoE) {
    int i = blockIdx.x * blockDim.x + threadIdx.x;
    if (i < twoE) out[i] = (long long)g_ei[i];
}

// ---------------- launch ----------------
extern "C" void kernel_launch(void* const* d_in, const int* in_sizes, int n_in,
                              void* d_out, int out_size) {
    const float* x   = (const float*)d_in[0];
    const void*  ei  = d_in[1];
    const float* w1l = (const float*)d_in[2];
    const float* w1r = (const float*)d_in[3];
    const float* b1  = (const float*)d_in[4];
    const float* w2l = (const float*)d_in[5];
    const float* w2r = (const float*)d_in[6];
    const float* b2  = (const float*)d_in[7];

    int N = in_sizes[0] / F_IN_;
    int twoE = in_sizes[1];
    int E = twoE / 2;
    float* out = (float*)d_out;

    cudaFuncSetAttribute(gemm_tc_kernel, cudaFuncAttributeMaxDynamicSharedMemorySize, SMEM_DYN);

    detect_kernel<<<1, 32>>>(ei, twoE);
    convert_ei_kernel<<<1024, 256>>>(ei, twoE);
    zero_small_kernel<<<(2 * N + 255) / 256, 256>>>(N);
    hist_kernel<<<(E + 255) / 256, 256>>>(E);
    int nsb = (N + SCAN_E - 1) / SCAN_E;
    scan1_kernel<<<nsb, SCAN_T>>>(N);
    scan2_kernel<<<1, 256>>>(nsb);
    scan3_kernel<<<(N + 255) / 256, 256>>>(N, E);
    fill_kernel<<<(E + 255) / 256, 256>>>(E);
    aggregate_kernel<<<(N * 32 + 255) / 256, 256>>>(x, N);
    prep_B_kernel<<<(HID_ * (KPAD / 8) + 255) / 256, 256>>>(w1l, w1r);
    gemm_tc_kernel<<<(N + 127) / 128, 256, SMEM_DYN>>>(b1, w2l, w2r, N);
    gather2_kernel<<<(N * 32 + 255) / 256, 256>>>(out, b2, N);

    long long rem = (long long)out_size - (long long)2 * N;
    if (rem >= (long long)twoE) {
        if (rem >= 2LL * twoE)
            ei_out_i64_kernel<<<(twoE + 255) / 256, 256>>>((long long*)(out + (size_t)2 * N), twoE);
        else
            ei_out_f32_kernel<<<(twoE + 255) / 256, 256>>>(out + (size_t)2 * N, twoE);
    }
}